// round 2
// baseline (speedup 1.0000x reference)
#include <cuda_runtime.h>
#include <cuda_bf16.h>

// Problem constants (from reference): 1024 bins, 3 columns, 16,777,216 rows.
#define N_BINS 1024
#define N_COLS 3
#define LUT_SIZE (N_BINS * N_COLS)

// Persistent scratch for the per-(column,bin) precomputed sigmoid values.
// Layout: g_lut[col * N_BINS + bin]
__device__ float g_lut[LUT_SIZE];

// ---------------------------------------------------------------------------
// Kernel 1: build the 3x1024 LUT.
//   lut[col][bin] = sigmoid( (ub[col] - logit(c_bin)) / (ub[col] - lb[col] + eps) )
// Precise logf/expf (not --use_fast_math intrinsics) to stay well under 1e-3.
// ---------------------------------------------------------------------------
__global__ void build_lut_kernel(const float* __restrict__ bin_centers,
                                 const float* __restrict__ lb,
                                 const float* __restrict__ ub) {
    int i = blockIdx.x * blockDim.x + threadIdx.x;
    if (i >= N_BINS) return;
    float c = bin_centers[i];
    float logit = logf(c / (1.0f - c));
#pragma unroll
    for (int col = 0; col < N_COLS; col++) {
        float u = ub[col];
        float l = lb[col];
        float x = (u - logit) / (u - l + 1e-4f);
        // sigmoid(x) = 1 / (1 + exp(-x))
        g_lut[col * N_BINS + i] = 1.0f / (1.0f + expf(-x));
    }
}

// ---------------------------------------------------------------------------
// Kernel 2: streaming gather-multiply.
// Each thread handles 4 rows = 12 consecutive int32 indices = 3 aligned int4
// loads, and writes one float4. LUT lives in shared memory (12 KB).
// ---------------------------------------------------------------------------
__global__ void __launch_bounds__(256)
gather_prod_kernel(const int4* __restrict__ idx4,
                   float4* __restrict__ out4,
                   int n4)  // number of float4 outputs (= rows / 4)
{
    __shared__ float lut[LUT_SIZE];
    for (int i = threadIdx.x; i < LUT_SIZE; i += blockDim.x)
        lut[i] = g_lut[i];
    __syncthreads();

    int t = blockIdx.x * blockDim.x + threadIdx.x;
    if (t >= n4) return;

    // 12 ints per thread: rows r0..r3, each (col0, col1, col2)
    int4 a = idx4[3 * t + 0];
    int4 b = idx4[3 * t + 1];
    int4 c = idx4[3 * t + 2];

    const float* l0 = lut;
    const float* l1 = lut + N_BINS;
    const float* l2 = lut + 2 * N_BINS;

    float4 o;
    o.x = l0[a.x] * l1[a.y] * l2[a.z];
    o.y = l0[a.w] * l1[b.x] * l2[b.y];
    o.z = l0[b.z] * l1[b.w] * l2[c.x];
    o.w = l0[c.y] * l1[c.z] * l2[c.w];

    out4[t] = o;
}

// Tail handler for row counts not divisible by 4 (defensive; N_DIFFS is).
__global__ void gather_prod_tail_kernel(const int* __restrict__ idx,
                                        float* __restrict__ out,
                                        int start_row, int n_rows)
{
    int r = start_row + blockIdx.x * blockDim.x + threadIdx.x;
    if (r >= n_rows) return;
    int i0 = idx[3 * r + 0];
    int i1 = idx[3 * r + 1];
    int i2 = idx[3 * r + 2];
    out[r] = g_lut[i0] * g_lut[N_BINS + i1] * g_lut[2 * N_BINS + i2];
}

extern "C" void kernel_launch(void* const* d_in, const int* in_sizes, int n_in,
                              void* d_out, int out_size)
{
    // metadata order: bin_centers (f32[1024]), observation_probability_index
    // (int32[n_rows*3]), lb (f32[3]), ub (f32[3]), operator_number (unused).
    const float* bin_centers = (const float*)d_in[0];
    const int*   idx         = (const int*)d_in[1];
    const float* lb          = (const float*)d_in[2];
    const float* ub          = (const float*)d_in[3];
    float*       out         = (float*)d_out;

    int n_rows = in_sizes[1] / 3;

    // 1) Build LUT (deterministic, rebuilt every call — no static guards).
    build_lut_kernel<<<(N_BINS + 255) / 256, 256>>>(bin_centers, lb, ub);

    // 2) Main streaming pass: 4 rows per thread.
    int n4 = n_rows / 4;
    if (n4 > 0) {
        int threads = 256;
        int blocks = (n4 + threads - 1) / threads;
        gather_prod_kernel<<<blocks, threads>>>(
            (const int4*)idx, (float4*)out, n4);
    }

    // 3) Tail (n_rows % 4 != 0) — not hit for this problem's shapes.
    int done = n4 * 4;
    if (done < n_rows) {
        int rem = n_rows - done;
        gather_prod_tail_kernel<<<(rem + 255) / 256, 256>>>(
            idx, out, done, n_rows);
    }
}

// round 3
// speedup vs baseline: 1.1874x; 1.1874x over previous
#include <cuda_runtime.h>
#include <cuda_bf16.h>

// Problem: out[r] = prod_{k=0..2} sigmoid((ub[k]-logit(bins[idx[r][k]]))/(ub[k]-lb[k]+1e-4))
// 1024 bins, 3 cols, 16.78M rows. Collapses to a 3x1024 LUT + streaming gather-product.

#define N_BINS   1024
#define N_COLS   3
#define LUT_SIZE (N_BINS * N_COLS)

__device__ float g_lut[LUT_SIZE];

// ---------------------------------------------------------------------------
// Kernel 1: build 3x1024 LUT with precise logf/expf.
// ---------------------------------------------------------------------------
__global__ void build_lut_kernel(const float* __restrict__ bin_centers,
                                 const float* __restrict__ lb,
                                 const float* __restrict__ ub) {
    int i = blockIdx.x * blockDim.x + threadIdx.x;
    if (i >= N_BINS) return;
    float c = bin_centers[i];
    float logit = logf(c / (1.0f - c));
#pragma unroll
    for (int col = 0; col < N_COLS; col++) {
        float u = ub[col];
        float l = lb[col];
        float x = (u - logit) / (u - l + 1e-4f);
        g_lut[col * N_BINS + i] = 1.0f / (1.0f + expf(-x));
    }
}

// ---------------------------------------------------------------------------
// Kernel 2: lane-major loads + warp-carry product stitching.
//
// Each warp iteration ("chunk") covers 128 rows = 384 ints = 96 int4.
// Loads are lane-major (minimal L1 wavefronts). Lane l in round j holds
// global ints g0..g0+3 with g0 = 384*chunk + 128*j + 4*lane.
// Since 384 % 3 == 0, col(g) = g % 3 = (lane + 2j + k) % 3.
// Each lane completes the row whose col-2 element it holds; the leading
// partial product of the next row is carried to lane+1 via shfl_up, and
// from lane 31 to lane 0 of the next round via shfl(.,31).
// ---------------------------------------------------------------------------
__device__ __forceinline__ float do_round(int4 v, const float* __restrict__ lut,
                                          int o0, int o1, int o2, int mj,
                                          float qprev, float* __restrict__ out,
                                          unsigned g0, int lane)
{
    // cols of the 4 elements are (mj, mj+1, mj+2, mj) mod 3 -> tables o0,o1,o2,o0
    float w0 = lut[o0 + v.x];
    float w1 = lut[o1 + v.y];
    float w2 = lut[o2 + v.z];
    float w3 = lut[o0 + v.w];

    float m01 = w0 * w1;
    float w23 = w2 * w3;

    // carry-out: product of trailing elements that belong to the NEXT row
    //   mj==0: rows (r,r,r,r+1) -> q = w3
    //   mj==1: rows (r,r,r+1,r+1) -> q = w2*w3
    //   mj==2: rows (r,r+1,r+1,r+1) -> carry unused by next lane (it starts fresh)
    float q = (mj == 0) ? w3 : w23;
    float qin = __shfl_up_sync(0xffffffffu, q, 1);
    if (lane == 0) qin = qprev;

    // complete the row whose col-2 element this lane holds
    float res;
    if (mj == 0)      res = m01 * w2;      // full row in-lane
    else if (mj == 1) res = qin * m01;     // qin = col0 from previous lane
    else              res = qin * w0;      // qin = col0*col1 from previous lane

    unsigned rA = g0 / 3u;                 // row of element 0 (floor works for all mj)
    out[rA] = res;
    if (mj == 2) out[rA + 1] = w1 * w23;   // this lane also holds a full row

    return __shfl_sync(0xffffffffu, q, 31);  // carry to lane 0 of next round
}

__global__ void __launch_bounds__(256)
carry_kernel(const int4* __restrict__ idx4, float* __restrict__ out, int nchunks)
{
    __shared__ float lut[LUT_SIZE];
    {
        const float4* src = (const float4*)g_lut;
        float4* dst = (float4*)lut;
#pragma unroll
        for (int i = threadIdx.x; i < LUT_SIZE / 4; i += 256)
            dst[i] = src[i];
    }
    __syncthreads();

    const int lane = threadIdx.x & 31;
    const int warpsTotal = gridDim.x * (256 / 32);
    int warpGlobal = blockIdx.x * (256 / 32) + (threadIdx.x >> 5);

    // per-lane column tables: off[i] = ((m+i)%3)*1024, m = lane%3
    const int m    = lane % 3;
    const int offA = m * N_BINS;
    const int offB = ((m + 1) % 3) * N_BINS;
    const int offC = ((m + 2) % 3) * N_BINS;
    // lane class per round: mj = (m + 2j) % 3
    const int m0 = m;
    const int m1 = (m + 2) % 3;
    const int m2 = (m + 1) % 3;

    for (int c = warpGlobal; c < nchunks; c += warpsTotal) {
        int base4 = c * 96;
        int4 v0 = __ldcs(idx4 + base4 + lane);
        int4 v1 = __ldcs(idx4 + base4 + 32 + lane);
        int4 v2 = __ldcs(idx4 + base4 + 64 + lane);

        unsigned Gw = (unsigned)c * 384u + 4u * (unsigned)lane;

        float qprev = 0.0f;  // round 0 lane 0 has mj==0 and never reads it
        qprev = do_round(v0, lut, offA, offB, offC, m0, qprev, out, Gw,        lane);
        qprev = do_round(v1, lut, offC, offA, offB, m1, qprev, out, Gw + 128u, lane);
        (void)  do_round(v2, lut, offB, offC, offA, m2, qprev, out, Gw + 256u, lane);
    }
}

// ---------------------------------------------------------------------------
// Tail: per-row scalar path for rows not covered by full 128-row chunks.
// ---------------------------------------------------------------------------
__global__ void gather_prod_tail_kernel(const int* __restrict__ idx,
                                        float* __restrict__ out,
                                        int start_row, int n_rows)
{
    int r = start_row + blockIdx.x * blockDim.x + threadIdx.x;
    if (r >= n_rows) return;
    int i0 = idx[3 * r + 0];
    int i1 = idx[3 * r + 1];
    int i2 = idx[3 * r + 2];
    out[r] = g_lut[i0] * g_lut[N_BINS + i1] * g_lut[2 * N_BINS + i2];
}

extern "C" void kernel_launch(void* const* d_in, const int* in_sizes, int n_in,
                              void* d_out, int out_size)
{
    const float* bin_centers = (const float*)d_in[0];
    const int*   idx         = (const int*)d_in[1];
    const float* lb          = (const float*)d_in[2];
    const float* ub          = (const float*)d_in[3];
    float*       out         = (float*)d_out;

    int n_rows = in_sizes[1] / 3;

    build_lut_kernel<<<(N_BINS + 255) / 256, 256>>>(bin_centers, lb, ub);

    int nchunks = n_rows / 128;   // 128 rows per warp-chunk
    if (nchunks > 0) {
        int blocks = 1184;        // ~single wave on 148-152 SMs; warps loop over chunks
        if (blocks * 8 > nchunks) blocks = (nchunks + 7) / 8;
        carry_kernel<<<blocks, 256>>>((const int4*)idx, out, nchunks);
    }

    int done = nchunks * 128;
    if (done < n_rows) {
        int rem = n_rows - done;
        gather_prod_tail_kernel<<<(rem + 255) / 256, 256>>>(idx, out, done, n_rows);
    }
}